// round 3
// baseline (speedup 1.0000x reference)
#include <cuda_runtime.h>
#include <cuda_bf16.h>

// Problem:
//   decoder_states: (32, 512, 1024) f32   d_in[0]
//   encoder_states: (32,1024, 1024) f32   d_in[1]
//   step:           scalar int (unused)   d_in[2]
//   mlp_weight:     (1, 2048) f32         d_in[3]  [0:1024]=w_enc, [1024:2048]=w_dec
//   mlp_bias:       (1,) f32              d_in[4]
//   out: (32, 512, 1024) f32 = dec_proj[b,t] + enc_proj[b,s] + bias

#define DIM        1024
#define BATCH      32
#define T_DEC      512
#define S_ENC      1024
#define N_DEC_ROWS (BATCH * T_DEC)   // 16384
#define N_ENC_ROWS (BATCH * S_ENC)   // 32768
#define N_ROWS     (N_DEC_ROWS + N_ENC_ROWS) // 49152

// Scratch for projections (allocation-free rule: __device__ globals)
__device__ float g_dec_proj[N_DEC_ROWS];
__device__ float g_enc_proj[N_ENC_ROWS];

// ---------------------------------------------------------------------------
// Kernel 1: row-wise dot products. One warp per row of 1024 f32.
// rows [0, 16384)          -> decoder rows   dot w_dec
// rows [16384, 49152)      -> encoder rows   dot w_enc
// ---------------------------------------------------------------------------
__global__ __launch_bounds__(256, 8)
void proj_kernel(const float4* __restrict__ dec4,
                 const float4* __restrict__ enc4,
                 const float4* __restrict__ w4)   // mlp_weight as float4 (512 of them)
{
    const int warp_id = (blockIdx.x * blockDim.x + threadIdx.x) >> 5;
    const int lane    = threadIdx.x & 31;
    if (warp_id >= N_ROWS) return;

    const float4* __restrict__ src;
    const float4* __restrict__ w;
    float* dst;
    if (warp_id < N_DEC_ROWS) {
        src = dec4 + (size_t)warp_id * (DIM / 4);
        w   = w4 + (DIM / 4);            // w_dec = mlp_weight[1024:]
        dst = g_dec_proj + warp_id;
    } else {
        const int e = warp_id - N_DEC_ROWS;
        src = enc4 + (size_t)e * (DIM / 4);
        w   = w4;                        // w_enc = mlp_weight[:1024]
        dst = g_enc_proj + e;
    }

    // 256 float4 per row / 32 lanes = 8 per lane. Independent loads -> MLP=8.
    float sum = 0.0f;
#pragma unroll
    for (int j = 0; j < 8; ++j) {
        const int idx = lane + 32 * j;
        const float4 v = __ldcs(src + idx);   // streaming: rows are read once
        const float4 ww = __ldg(w + idx);     // weight: tiny, cache hard
        sum = fmaf(v.x, ww.x, sum);
        sum = fmaf(v.y, ww.y, sum);
        sum = fmaf(v.z, ww.z, sum);
        sum = fmaf(v.w, ww.w, sum);
    }

    // warp butterfly reduce
#pragma unroll
    for (int off = 16; off > 0; off >>= 1)
        sum += __shfl_xor_sync(0xFFFFFFFFu, sum, off);

    if (lane == 0) *dst = sum;
}

// ---------------------------------------------------------------------------
// Kernel 2: broadcast add + write.
// One block per (b, t) output row: 256 threads x float4 = 1024 f32.
// dec_proj[b,t] is one scalar per block; enc_proj[b,:] (4 KB) is L2-resident.
// ---------------------------------------------------------------------------
__global__ __launch_bounds__(256, 8)
void bcast_kernel(float4* __restrict__ out4,
                  const float* __restrict__ bias)
{
    const int row = blockIdx.x;            // b*512 + t, 0..16383
    const int b   = row >> 9;              // /512
    const int s4  = threadIdx.x;           // 0..255 -> s = 4*s4

    const float d = g_dec_proj[row] + __ldg(bias);
    const float4 e = *((const float4*)g_enc_proj + b * (S_ENC / 4) + s4);

    float4 o;
    o.x = d + e.x;
    o.y = d + e.y;
    o.z = d + e.z;
    o.w = d + e.w;
    __stcs(out4 + (size_t)row * (DIM / 4) + s4, o);   // streaming store
}

extern "C" void kernel_launch(void* const* d_in, const int* in_sizes, int n_in,
                              void* d_out, int out_size)
{
    const float4* dec4 = (const float4*)d_in[0];
    const float4* enc4 = (const float4*)d_in[1];
    // d_in[2] = step (unused)
    const float4* w4   = (const float4*)d_in[3];
    const float*  bias = (const float*)d_in[4];
    float4* out4 = (float4*)d_out;

    // Kernel 1: 49152 warps -> 49152*32/256 = 6144 blocks
    proj_kernel<<<(N_ROWS * 32) / 256, 256>>>(dec4, enc4, w4);

    // Kernel 2: one block per output row
    bcast_kernel<<<N_DEC_ROWS, 256>>>(out4, bias);
}

// round 5
// speedup vs baseline: 1.0694x; 1.0694x over previous
#include <cuda_runtime.h>
#include <cuda_bf16.h>

// Problem:
//   decoder_states: (32, 512, 1024) f32   d_in[0]
//   encoder_states: (32,1024, 1024) f32   d_in[1]
//   step:           scalar int (unused)   d_in[2]
//   mlp_weight:     (1, 2048) f32         d_in[3]  [0:1024]=w_enc, [1024:2048]=w_dec
//   mlp_bias:       (1,) f32              d_in[4]
//   out[b,t,s] = dot(dec[b,t], w_dec) + dot(enc[b,s], w_enc) + bias

#define DIM        1024
#define BATCH      32
#define T_DEC      512
#define S_ENC      1024
#define N_DEC_ROWS (BATCH * T_DEC)   // 16384
#define N_ENC_ROWS (BATCH * S_ENC)   // 32768
#define ROWS_PER_BLK 8               // decoder rows per block in fused kernel

// Scratch (allocation-free rule: __device__ global)
__device__ float g_enc_proj[N_ENC_ROWS];

// ---------------------------------------------------------------------------
// Kernel A: encoder projection. One warp per row of 1024 f32.
// 32768 rows -> 4096 blocks x 256 threads.
// No min-blocks launch bound: the 32-reg cap it implies would serialize the
// 8 in-flight float4 loads (R3 theory for the 4.7 TB/s read ceiling).
// ---------------------------------------------------------------------------
__global__ __launch_bounds__(256)
void enc_proj_kernel(const float4* __restrict__ enc4,
                     const float4* __restrict__ w4)   // w_enc = mlp_weight[0:1024]
{
    const int warp_id = (blockIdx.x * blockDim.x + threadIdx.x) >> 5;
    const int lane    = threadIdx.x & 31;

    const float4* __restrict__ src = enc4 + (size_t)warp_id * (DIM / 4);

    // 8 independent float4 loads per lane (MLP=8), 2 accumulators.
    float s0 = 0.0f, s1 = 0.0f;
#pragma unroll
    for (int j = 0; j < 8; j += 2) {
        const float4 a  = __ldcs(src + lane + 32 * j);
        const float4 wa = __ldg (w4  + lane + 32 * j);
        const float4 b  = __ldcs(src + lane + 32 * (j + 1));
        const float4 wb = __ldg (w4  + lane + 32 * (j + 1));
        s0 = fmaf(a.x, wa.x, s0); s0 = fmaf(a.y, wa.y, s0);
        s0 = fmaf(a.z, wa.z, s0); s0 = fmaf(a.w, wa.w, s0);
        s1 = fmaf(b.x, wb.x, s1); s1 = fmaf(b.y, wb.y, s1);
        s1 = fmaf(b.z, wb.z, s1); s1 = fmaf(b.w, wb.w, s1);
    }
    float sum = s0 + s1;
#pragma unroll
    for (int off = 16; off > 0; off >>= 1)
        sum += __shfl_xor_sync(0xFFFFFFFFu, sum, off);

    if (lane == 0) g_enc_proj[warp_id] = sum;
}

// ---------------------------------------------------------------------------
// Kernel B: fused decoder projection + broadcast write.
// Block = 256 threads (8 warps) handles (batch b, 8 consecutive t rows):
//   - stage enc_proj[b,:] (4 KB) in smem (L2-resident, reused 64x per batch)
//   - warp w computes dot(dec[b, t0+w], w_dec)  (reads 8 x 4 KB)
//   - all threads write 8 output rows (8 x 4 KB, independent streaming stores)
// Grid = 16384 / 8 = 2048 blocks.
// ---------------------------------------------------------------------------
__global__ __launch_bounds__(256)
void fused_dec_kernel(const float4* __restrict__ dec4,
                      const float4* __restrict__ w4,    // full mlp_weight
                      const float*  __restrict__ bias,
                      float4* __restrict__ out4)
{
    __shared__ float4 esm[S_ENC / 4];        // 4 KB: enc_proj row for batch b
    __shared__ float  dsm[ROWS_PER_BLK];

    const int blk  = blockIdx.x;             // 0..2047
    const int b    = blk >> 6;               // 64 chunks of 8 rows per batch
    const int t0   = (blk & 63) * ROWS_PER_BLK;
    const int tid  = threadIdx.x;
    const int w    = tid >> 5;
    const int lane = tid & 31;

    // stage enc_proj[b, :] -> smem (256 x float4 = 4 KB); hit L2 hard, not streaming
    esm[tid] = __ldg((const float4*)g_enc_proj + b * (S_ENC / 4) + tid);

    const float bi = __ldg(bias);            // off the reduce critical path

    // warp-per-row decoder dot
    const int row = (b << 9) + t0 + w;       // b*512 + t
    const float4* __restrict__ src = dec4 + (size_t)row * (DIM / 4);
    const float4* __restrict__ wd  = w4 + (DIM / 4);   // w_dec

    float s0 = 0.0f, s1 = 0.0f;
#pragma unroll
    for (int j = 0; j < 8; j += 2) {
        const float4 a  = __ldcs(src + lane + 32 * j);
        const float4 wa = __ldg (wd  + lane + 32 * j);
        const float4 c  = __ldcs(src + lane + 32 * (j + 1));
        const float4 wb = __ldg (wd  + lane + 32 * (j + 1));
        s0 = fmaf(a.x, wa.x, s0); s0 = fmaf(a.y, wa.y, s0);
        s0 = fmaf(a.z, wa.z, s0); s0 = fmaf(a.w, wa.w, s0);
        s1 = fmaf(c.x, wb.x, s1); s1 = fmaf(c.y, wb.y, s1);
        s1 = fmaf(c.z, wb.z, s1); s1 = fmaf(c.w, wb.w, s1);
    }
    float sum = s0 + s1;
#pragma unroll
    for (int off = 16; off > 0; off >>= 1)
        sum += __shfl_xor_sync(0xFFFFFFFFu, sum, off);

    if (lane == 0) dsm[w] = sum + bi;
    __syncthreads();

    // write 8 output rows; e is invariant across rows, stores independent
    const float4 e = esm[tid];
    float4* __restrict__ obase = out4 + (size_t)((b << 9) + t0) * (DIM / 4) + tid;
#pragma unroll
    for (int r = 0; r < ROWS_PER_BLK; ++r) {
        const float d = dsm[r];
        float4 o;
        o.x = d + e.x; o.y = d + e.y; o.z = d + e.z; o.w = d + e.w;
        __stcs(obase + (size_t)r * (DIM / 4), o);
    }
}

extern "C" void kernel_launch(void* const* d_in, const int* in_sizes, int n_in,
                              void* d_out, int out_size)
{
    const float4* dec4 = (const float4*)d_in[0];
    const float4* enc4 = (const float4*)d_in[1];
    // d_in[2] = step (unused)
    const float4* w4   = (const float4*)d_in[3];
    const float*  bias = (const float*)d_in[4];
    float4* out4 = (float4*)d_out;

    // A: 32768 warps -> 4096 blocks
    enc_proj_kernel<<<(N_ENC_ROWS * 32) / 256, 256>>>(enc4, w4);
    // B: 2048 blocks, 8 decoder rows each
    fused_dec_kernel<<<N_DEC_ROWS / ROWS_PER_BLK, 256>>>(dec4, w4, bias, out4);
}